// round 2
// baseline (speedup 1.0000x reference)
#include <cuda_runtime.h>
#include <math.h>

// Problem constants (fixed by the reference: R=32, G=R^3, N=256, SH_DIM=9)
#define GRID_G   32768
#define NPTS     256
#define PTS_PER_BLK 64
#define TPB      256

// SH normalization constants (degree 2, real basis, matching reference)
#define C0  0.28209479177387814f   // 0.5*sqrt(1/pi)
#define C1  0.4886025119029199f    // sqrt(3/(4pi))
#define C2A 0.5462742152960396f    // 0.5*sqrt(15/(4pi))
#define C2B 0.15769578262626002f   // 0.5*sqrt(5/(16pi))
#define C2C 0.2730689607973162f    // 0.5*sqrt(15/(16pi))

__global__ __launch_bounds__(TPB) void gausssplat_kernel(
    const float* __restrict__ points,     // [N,3]
    const float* __restrict__ positions,  // [G,3]
    const float* __restrict__ scales,     // [G,3]
    const float* __restrict__ rotations,  // [G,4]
    const float* __restrict__ opacity,    // [G]
    const float* __restrict__ sh,         // [G,9]
    float* __restrict__ out)              // [N*G rgb][G sigma]
{
    const int g     = blockIdx.x * TPB + threadIdx.x;
    const int nbase = blockIdx.y * PTS_PER_BLK;

    // Stage this block's chunk of query points (already scaled by 1/4)
    __shared__ float spx[PTS_PER_BLK], spy[PTS_PER_BLK], spz[PTS_PER_BLK];
    if (threadIdx.x < PTS_PER_BLK) {
        const int n = nbase + threadIdx.x;
        spx[threadIdx.x] = points[3*n + 0] * 0.25f;
        spy[threadIdx.x] = points[3*n + 1] * 0.25f;
        spz[threadIdx.x] = points[3*n + 2] * 0.25f;
    }
    __syncthreads();

    // ---- Per-gaussian preprocessing (amortized over PTS_PER_BLK points) ----
    const float px = positions[3*g + 0];
    const float py = positions[3*g + 1];
    const float pz = positions[3*g + 2];

    const float isx = 1.0f / (scales[3*g + 0] + 1e-6f);
    const float isy = 1.0f / (scales[3*g + 1] + 1e-6f);
    const float isz = 1.0f / (scales[3*g + 2] + 1e-6f);

    const float q0 = rotations[4*g + 0];
    const float q1 = rotations[4*g + 1];
    const float q2 = rotations[4*g + 2];
    const float q3 = rotations[4*g + 3];

    // Quaternion -> matrix, NO normalization (matches reference exactly)
    const float r00 = 1.0f - 2.0f*(q2*q2 + q3*q3);
    const float r01 = 2.0f*(q1*q2 - q0*q3);
    const float r02 = 2.0f*(q1*q3 + q0*q2);
    const float r10 = 2.0f*(q1*q2 + q0*q3);
    const float r11 = 1.0f - 2.0f*(q1*q1 + q3*q3);
    const float r12 = 2.0f*(q2*q3 - q0*q1);
    const float r20 = 2.0f*(q1*q3 - q0*q2);
    const float r21 = 2.0f*(q2*q3 + q0*q1);
    const float r22 = 1.0f - 2.0f*(q1*q1 + q2*q2);

    // Fold SH normalization constants into the per-g coefficients once
    const float s0 = sh[9*g + 0] * C0;
    const float s1 = sh[9*g + 1] * C1;   // * y
    const float s2 = sh[9*g + 2] * C1;   // * z
    const float s3 = sh[9*g + 3] * C1;   // * x
    const float s4 = sh[9*g + 4] * C2A;  // * xy
    const float s5 = sh[9*g + 5] * C2A;  // * yz
    const float s6 = sh[9*g + 6] * C2B;  // * (3z^2-1)
    const float s7 = sh[9*g + 7] * C2A;  // * xz
    const float s8 = sh[9*g + 8] * C2C;  // * (x^2-y^2)

    // sigma = softplus(opacity), written once (only by the first n-chunk)
    if (blockIdx.y == 0) {
        const float o = opacity[g];
        out[(size_t)NPTS * GRID_G + g] =
            fmaxf(o, 0.0f) + log1pf(__expf(-fabsf(o)));
    }

    float* __restrict__ orow = out + (size_t)nbase * GRID_G + g;

    #pragma unroll 4
    for (int i = 0; i < PTS_PER_BLK; ++i) {
        // diff scaled by inverse scale
        const float dx = (spx[i] - px) * isx;
        const float dy = (spy[i] - py) * isy;
        const float dz = (spz[i] - pz) * isz;

        // rotated_i = sum_j R[i][j] * ds[j]
        const float rx = fmaf(r00, dx, fmaf(r01, dy, r02 * dz));
        const float ry = fmaf(r10, dx, fmaf(r11, dy, r12 * dz));
        const float rz = fmaf(r20, dx, fmaf(r21, dy, r22 * dz));

        const float n2  = fmaf(rx, rx, fmaf(ry, ry, rz * rz));
        const float inv = rsqrtf(n2);
        const float x = rx * inv, y = ry * inv, z = rz * inv;

        // SH dot product (constants already folded into s_i)
        float v = s0;
        v = fmaf(s1, y, v);
        v = fmaf(s2, z, v);
        v = fmaf(s3, x, v);
        v = fmaf(s4, x * y, v);
        v = fmaf(s5, y * z, v);
        v = fmaf(s7, x * z, v);
        v = fmaf(s6, fmaf(3.0f, z * z, -1.0f), v);
        v = fmaf(s8, fmaf(x, x, -(y * y)), v);

        // sigmoid
        const float rgb = 1.0f / (1.0f + __expf(-v));
        orow[(size_t)i * GRID_G] = rgb;
    }
}

extern "C" void kernel_launch(void* const* d_in, const int* in_sizes, int n_in,
                              void* d_out, int out_size) {
    const float* points    = (const float*)d_in[0];
    const float* positions = (const float*)d_in[1];
    const float* scales    = (const float*)d_in[2];
    const float* rotations = (const float*)d_in[3];
    const float* opacity   = (const float*)d_in[4];
    const float* sh        = (const float*)d_in[5];
    float* out = (float*)d_out;

    dim3 grid(GRID_G / TPB, NPTS / PTS_PER_BLK);
    gausssplat_kernel<<<grid, TPB>>>(points, positions, scales, rotations,
                                     opacity, sh, out);
}

// round 3
// speedup vs baseline: 1.4717x; 1.4717x over previous
#include <cuda_runtime.h>
#include <math.h>

// Problem constants (fixed by reference: R=32, G=32768, N=256, SH_DIM=9)
#define G_TOTAL 32768
#define NPTS    256
#define TPB     128
#define GPT     2     // gaussians per thread
#define PPB     16    // points per block

// SH normalization constants (degree 2, real basis)
#define C0  0.28209479177387814f
#define C1  0.4886025119029199f
#define C2A 0.5462742152960396f
#define C2B 0.15769578262626002f
#define C2C 0.2730689607973162f

__global__ __launch_bounds__(TPB) void gausssplat_kernel(
    const float* __restrict__ points,     // [N,3]
    const float* __restrict__ positions,  // [G,3]
    const float* __restrict__ scales,     // [G,3]
    const float* __restrict__ rotations,  // [G,4]
    const float* __restrict__ opacity,    // [G]
    const float* __restrict__ sh,         // [G,9]
    float* __restrict__ out)              // [N*G rgb][G sigma]
{
    const int g0    = (blockIdx.x * TPB + threadIdx.x) * GPT;
    const int nbase = blockIdx.y * PPB;

    // Stage this block's point chunk as float4 (pre-scaled by 1/4)
    __shared__ float4 sp[PPB];
    if (threadIdx.x < PPB) {
        const int n = nbase + threadIdx.x;
        sp[threadIdx.x] = make_float4(points[3*n + 0] * 0.25f,
                                      points[3*n + 1] * 0.25f,
                                      points[3*n + 2] * 0.25f, 0.0f);
    }
    __syncthreads();

    // ---- Per-gaussian precompute: M = R*diag(1/s), c = M*pos, folded SH ----
    float m00[GPT], m01[GPT], m02[GPT];
    float m10[GPT], m11[GPT], m12[GPT];
    float m20[GPT], m21[GPT], m22[GPT];
    float ncx[GPT], ncy[GPT], ncz[GPT];
    float s1c[GPT], s2c[GPT], s3c[GPT];
    float s4c[GPT], s5c[GPT], s7c[GPT];
    float s63[GPT], s8c[GPT], bse[GPT];

    #pragma unroll
    for (int k = 0; k < GPT; ++k) {
        const int g = g0 + k;

        const float isx = __fdividef(1.0f, scales[3*g + 0] + 1e-6f);
        const float isy = __fdividef(1.0f, scales[3*g + 1] + 1e-6f);
        const float isz = __fdividef(1.0f, scales[3*g + 2] + 1e-6f);

        const float q0 = rotations[4*g + 0];
        const float q1 = rotations[4*g + 1];
        const float q2 = rotations[4*g + 2];
        const float q3 = rotations[4*g + 3];

        // Quaternion -> matrix (no normalization, matches reference),
        // columns scaled by the inverse scale: M = R * diag(is)
        m00[k] = (1.0f - 2.0f*(q2*q2 + q3*q3)) * isx;
        m01[k] = (2.0f*(q1*q2 - q0*q3))        * isy;
        m02[k] = (2.0f*(q1*q3 + q0*q2))        * isz;
        m10[k] = (2.0f*(q1*q2 + q0*q3))        * isx;
        m11[k] = (1.0f - 2.0f*(q1*q1 + q3*q3)) * isy;
        m12[k] = (2.0f*(q2*q3 - q0*q1))        * isz;
        m20[k] = (2.0f*(q1*q3 - q0*q2))        * isx;
        m21[k] = (2.0f*(q2*q3 + q0*q1))        * isy;
        m22[k] = (1.0f - 2.0f*(q1*q1 + q2*q2)) * isz;

        const float px = positions[3*g + 0];
        const float py = positions[3*g + 1];
        const float pz = positions[3*g + 2];
        ncx[k] = -(m00[k]*px + m01[k]*py + m02[k]*pz);
        ncy[k] = -(m10[k]*px + m11[k]*py + m12[k]*pz);
        ncz[k] = -(m20[k]*px + m21[k]*py + m22[k]*pz);

        // Fold SH norm constants; base absorbs the -C2B*sh6 from (3z^2-1)
        s1c[k] = sh[9*g + 1] * C1;
        s2c[k] = sh[9*g + 2] * C1;
        s3c[k] = sh[9*g + 3] * C1;
        s4c[k] = sh[9*g + 4] * C2A;
        s5c[k] = sh[9*g + 5] * C2A;
        s63[k] = sh[9*g + 6] * (3.0f * C2B);
        s7c[k] = sh[9*g + 7] * C2A;
        s8c[k] = sh[9*g + 8] * C2C;
        bse[k] = fmaf(sh[9*g + 0], C0, -(sh[9*g + 6] * C2B));
    }

    // sigma = softplus(opacity), written by the first n-chunk only
    if (blockIdx.y == 0) {
        float2 sg;
        const float o0 = opacity[g0];
        const float o1 = opacity[g0 + 1];
        sg.x = fmaxf(o0, 0.0f) + log1pf(__expf(-fabsf(o0)));
        sg.y = fmaxf(o1, 0.0f) + log1pf(__expf(-fabsf(o1)));
        *(float2*)(out + (size_t)NPTS * G_TOTAL + g0) = sg;
    }

    float* __restrict__ orow = out + (size_t)nbase * G_TOTAL + g0;

    #pragma unroll
    for (int i = 0; i < PPB; ++i) {
        const float4 p = sp[i];
        float res[GPT];

        #pragma unroll
        for (int k = 0; k < GPT; ++k) {
            // rotated+scaled diff: M*p - c (9 FMA)
            const float rx = fmaf(m00[k], p.x, fmaf(m01[k], p.y, fmaf(m02[k], p.z, ncx[k])));
            const float ry = fmaf(m10[k], p.x, fmaf(m11[k], p.y, fmaf(m12[k], p.z, ncy[k])));
            const float rz = fmaf(m20[k], p.x, fmaf(m21[k], p.y, fmaf(m22[k], p.z, ncz[k])));

            const float n2   = fmaf(rx, rx, fmaf(ry, ry, rz * rz));
            const float inv  = rsqrtf(n2);
            const float inv2 = inv * inv;

            // degree-1 part (on unnormalized vector)
            const float lin = fmaf(s1c[k], ry, fmaf(s2c[k], rz, s3c[k] * rx));

            // degree-2 part (on unnormalized vector)
            const float xy = rx * ry, yz = ry * rz, xz = rx * rz;
            const float zz = rz * rz, x2 = rx * rx, y2 = ry * ry;
            float q = s8c[k] * x2;
            q = fmaf(-s8c[k], y2, q);
            q = fmaf(s4c[k], xy, q);
            q = fmaf(s5c[k], yz, q);
            q = fmaf(s7c[k], xz, q);
            q = fmaf(s63[k], zz, q);

            const float v = fmaf(q, inv2, fmaf(lin, inv, bse[k]));

            // sigmoid
            const float e = __expf(-v);
            res[k] = __fdividef(1.0f, 1.0f + e);
        }

        *(float2*)&orow[(size_t)i * G_TOTAL] = make_float2(res[0], res[1]);
    }
}

extern "C" void kernel_launch(void* const* d_in, const int* in_sizes, int n_in,
                              void* d_out, int out_size) {
    const float* points    = (const float*)d_in[0];
    const float* positions = (const float*)d_in[1];
    const float* scales    = (const float*)d_in[2];
    const float* rotations = (const float*)d_in[3];
    const float* opacity   = (const float*)d_in[4];
    const float* sh        = (const float*)d_in[5];
    float* out = (float*)d_out;

    dim3 grid(G_TOTAL / (TPB * GPT), NPTS / PPB);
    gausssplat_kernel<<<grid, TPB>>>(points, positions, scales, rotations,
                                     opacity, sh, out);
}

// round 5
// speedup vs baseline: 1.4741x; 1.0017x over previous
#include <cuda_runtime.h>
#include <math.h>

// Problem constants (fixed by reference: R=32, G=32768, N=256, SH_DIM=9)
#define G_TOTAL 32768
#define NPTS    256
#define TPB     128
#define GPT     2     // gaussians per thread (packed into f32x2)
#define PPB     16    // points per block

// SH normalization constants (degree 2, real basis)
#define C0  0.28209479177387814f
#define C1  0.4886025119029199f
#define C2A 0.5462742152960396f
#define C2B 0.15769578262626002f
#define C2C 0.2730689607973162f

typedef unsigned long long u64;

// ---- packed f32x2 helpers (sm_100+ PTX; ptxas won't auto-fuse these) ----
__device__ __forceinline__ u64 pk2(float a, float b) {
    u64 r; asm("mov.b64 %0, {%1,%2};" : "=l"(r) : "f"(a), "f"(b)); return r;
}
__device__ __forceinline__ void unpk(u64 p, float& a, float& b) {
    asm("mov.b64 {%0,%1}, %2;" : "=f"(a), "=f"(b) : "l"(p));
}
__device__ __forceinline__ u64 f2fma(u64 a, u64 b, u64 c) {
    u64 r; asm("fma.rn.f32x2 %0, %1, %2, %3;" : "=l"(r) : "l"(a), "l"(b), "l"(c)); return r;
}
__device__ __forceinline__ u64 f2mul(u64 a, u64 b) {
    u64 r; asm("mul.rn.f32x2 %0, %1, %2;" : "=l"(r) : "l"(a), "l"(b)); return r;
}
__device__ __forceinline__ float rsq_approx(float x) {
    float r; asm("rsqrt.approx.f32 %0, %1;" : "=f"(r) : "f"(x)); return r;
}
__device__ __forceinline__ float ex2_approx(float x) {
    float r; asm("ex2.approx.f32 %0, %1;" : "=f"(r) : "f"(x)); return r;
}
__device__ __forceinline__ float rcp_approx(float x) {
    float r; asm("rcp.approx.f32 %0, %1;" : "=f"(r) : "f"(x)); return r;
}

__global__ __launch_bounds__(TPB) void gausssplat_kernel(
    const float* __restrict__ points,     // [N,3]
    const float* __restrict__ positions,  // [G,3]
    const float* __restrict__ scales,     // [G,3]
    const float* __restrict__ rotations,  // [G,4]
    const float* __restrict__ opacity,    // [G]
    const float* __restrict__ sh,         // [G,9]
    float* __restrict__ out)              // [N*G rgb][G sigma]
{
    const int g0    = (blockIdx.x * TPB + threadIdx.x) * GPT;
    const int nbase = blockIdx.y * PPB;

    // Broadcast-duplicated point chunk: row = {x,x,y,y,z,z,_,_} (32B stride)
    __shared__ float sp[PPB][8];
    if (threadIdx.x < PPB) {
        const int n = nbase + threadIdx.x;
        const float x = points[3*n + 0] * 0.25f;
        const float y = points[3*n + 1] * 0.25f;
        const float z = points[3*n + 2] * 0.25f;
        sp[threadIdx.x][0] = x; sp[threadIdx.x][1] = x;
        sp[threadIdx.x][2] = y; sp[threadIdx.x][3] = y;
        sp[threadIdx.x][4] = z; sp[threadIdx.x][5] = z;
    }
    __syncthreads();

    // ---- Per-gaussian precompute (scalar), then pack pairs into f32x2 ----
    float m00[2], m01[2], m02[2], m10[2], m11[2], m12[2], m20[2], m21[2], m22[2];
    float ncx[2], ncy[2], ncz[2];
    float c1y[2], c1z[2], c1x[2], cxy[2], cyz[2], cxz[2], c8[2], c63[2], cb[2];

    #pragma unroll
    for (int k = 0; k < GPT; ++k) {
        const int g = g0 + k;
        const float isx = rcp_approx(scales[3*g + 0] + 1e-6f);
        const float isy = rcp_approx(scales[3*g + 1] + 1e-6f);
        const float isz = rcp_approx(scales[3*g + 2] + 1e-6f);

        const float q0 = rotations[4*g + 0];
        const float q1 = rotations[4*g + 1];
        const float q2 = rotations[4*g + 2];
        const float q3 = rotations[4*g + 3];

        // M = R * diag(1/s)   (quat->matrix without normalization, as reference)
        m00[k] = (1.0f - 2.0f*(q2*q2 + q3*q3)) * isx;
        m01[k] = (2.0f*(q1*q2 - q0*q3))        * isy;
        m02[k] = (2.0f*(q1*q3 + q0*q2))        * isz;
        m10[k] = (2.0f*(q1*q2 + q0*q3))        * isx;
        m11[k] = (1.0f - 2.0f*(q1*q1 + q3*q3)) * isy;
        m12[k] = (2.0f*(q2*q3 - q0*q1))        * isz;
        m20[k] = (2.0f*(q1*q3 - q0*q2))        * isx;
        m21[k] = (2.0f*(q2*q3 + q0*q1))        * isy;
        m22[k] = (1.0f - 2.0f*(q1*q1 + q2*q2)) * isz;

        const float px = positions[3*g + 0];
        const float py = positions[3*g + 1];
        const float pz = positions[3*g + 2];
        ncx[k] = -(m00[k]*px + m01[k]*py + m02[k]*pz);
        ncy[k] = -(m10[k]*px + m11[k]*py + m12[k]*pz);
        ncz[k] = -(m20[k]*px + m21[k]*py + m22[k]*pz);

        c1y[k] = sh[9*g + 1] * C1;
        c1z[k] = sh[9*g + 2] * C1;
        c1x[k] = sh[9*g + 3] * C1;
        cxy[k] = sh[9*g + 4] * C2A;
        cyz[k] = sh[9*g + 5] * C2A;
        c63[k] = sh[9*g + 6] * (3.0f * C2B);
        cxz[k] = sh[9*g + 7] * C2A;
        c8[k]  = sh[9*g + 8] * C2C;
        cb[k]  = fmaf(sh[9*g + 0], C0, -(sh[9*g + 6] * C2B));
    }

    const u64 M00 = pk2(m00[0], m00[1]), M01 = pk2(m01[0], m01[1]), M02 = pk2(m02[0], m02[1]);
    const u64 M10 = pk2(m10[0], m10[1]), M11 = pk2(m11[0], m11[1]), M12 = pk2(m12[0], m12[1]);
    const u64 M20 = pk2(m20[0], m20[1]), M21 = pk2(m21[0], m21[1]), M22 = pk2(m22[0], m22[1]);
    const u64 NCX = pk2(ncx[0], ncx[1]), NCY = pk2(ncy[0], ncy[1]), NCZ = pk2(ncz[0], ncz[1]);
    const u64 S1  = pk2(c1y[0], c1y[1]), S2  = pk2(c1z[0], c1z[1]), S3  = pk2(c1x[0], c1x[1]);
    const u64 S4  = pk2(cxy[0], cxy[1]), S5  = pk2(cyz[0], cyz[1]), S7  = pk2(cxz[0], cxz[1]);
    const u64 S8  = pk2(c8[0],  c8[1]),  NS8 = pk2(-c8[0], -c8[1]);
    const u64 S63 = pk2(c63[0], c63[1]), BSE = pk2(cb[0],  cb[1]);
    const u64 NL2E = pk2(-1.4426950408889634f, -1.4426950408889634f); // -log2(e)

    // sigma = softplus(opacity) once
    if (blockIdx.y == 0) {
        float2 sg;
        const float o0 = opacity[g0];
        const float o1 = opacity[g0 + 1];
        sg.x = fmaxf(o0, 0.0f) + log1pf(__expf(-fabsf(o0)));
        sg.y = fmaxf(o1, 0.0f) + log1pf(__expf(-fabsf(o1)));
        *(float2*)(out + (size_t)NPTS * G_TOTAL + g0) = sg;
    }

    float* __restrict__ orow = out + (size_t)nbase * G_TOTAL + g0;

    #pragma unroll
    for (int i = 0; i < PPB; ++i) {
        const u64 PX = *(const u64*)&sp[i][0];
        const u64 PY = *(const u64*)&sp[i][2];
        const u64 PZ = *(const u64*)&sp[i][4];

        // rotated+scaled diff: M*p - c  (9 packed FMA)
        const u64 rx = f2fma(M00, PX, f2fma(M01, PY, f2fma(M02, PZ, NCX)));
        const u64 ry = f2fma(M10, PX, f2fma(M11, PY, f2fma(M12, PZ, NCY)));
        const u64 rz = f2fma(M20, PX, f2fma(M21, PY, f2fma(M22, PZ, NCZ)));

        const u64 zz = f2mul(rz, rz);
        const u64 n2 = f2fma(rx, rx, f2fma(ry, ry, zz));

        float n2a, n2b; unpk(n2, n2a, n2b);
        const u64 inv = pk2(rsq_approx(n2a), rsq_approx(n2b));

        // degree-1 (unnormalized)
        const u64 lin = f2fma(S1, ry, f2fma(S2, rz, f2mul(S3, rx)));
        // degree-2 (unnormalized, Horner): x(s8x+s4y+s7z) + y(s5z-s8y) + s63 z^2
        const u64 t1 = f2fma(S8, rx, f2fma(S4, ry, f2mul(S7, rz)));
        const u64 t2 = f2fma(NS8, ry, f2mul(S5, rz));
        const u64 q  = f2fma(rx, t1, f2fma(ry, t2, f2mul(S63, zz)));

        // v = bse + inv*(lin + inv*q)
        const u64 v = f2fma(inv, f2fma(q, inv, lin), BSE);

        // sigmoid: e = 2^(-v*log2e); rgb = 1/(1+e)
        const u64 t = f2mul(v, NL2E);
        float ta, tb; unpk(t, ta, tb);
        const float ea = ex2_approx(ta);
        const float eb = ex2_approx(tb);
        float2 res;
        res.x = rcp_approx(1.0f + ea);
        res.y = rcp_approx(1.0f + eb);

        *(float2*)&orow[(size_t)i * G_TOTAL] = res;
    }
}

extern "C" void kernel_launch(void* const* d_in, const int* in_sizes, int n_in,
                              void* d_out, int out_size) {
    const float* points    = (const float*)d_in[0];
    const float* positions = (const float*)d_in[1];
    const float* scales    = (const float*)d_in[2];
    const float* rotations = (const float*)d_in[3];
    const float* opacity   = (const float*)d_in[4];
    const float* sh        = (const float*)d_in[5];
    float* out = (float*)d_out;

    dim3 grid(G_TOTAL / (TPB * GPT), NPTS / PPB);
    gausssplat_kernel<<<grid, TPB>>>(points, positions, scales, rotations,
                                     opacity, sh, out);
}